// round 10
// baseline (speedup 1.0000x reference)
#include <cuda_runtime.h>
#include <cuda_bf16.h>
#include <cstdint>

#define BB 32
#define TT 512
#define DD 256
#define FF 256
#define MM (BB * TT)          // 16384
#define KTOT 768
#define MEL 2304
#define OUT_GATHER_ELEMS (BB * MEL * DD)   // 18874368

// ---------------- device scratch (no allocs allowed) ----------------
__device__ __nv_bfloat16 g_w1h[FF * KTOT];
__device__ __nv_bfloat16 g_w1l[FF * KTOT];
__device__ __nv_bfloat16 g_w2h[FF * KTOT];
__device__ __nv_bfloat16 g_w2l[FF * KTOT];
__device__ __nv_bfloat16 g_xh[MM * DD];
__device__ __nv_bfloat16 g_xl[MM * DD];
__device__ __nv_bfloat16 g_h1h[MM * FF];
__device__ __nv_bfloat16 g_h1l[MM * FF];
__device__ int g_cum[BB * TT];

// ---------------- helpers ----------------
__device__ __forceinline__ uint32_t smem_u32(const void* p) {
    uint32_t a;
    asm("{ .reg .u64 t; cvta.to.shared.u64 t, %1; cvt.u32.u64 %0, t; }" : "=r"(a) : "l"(p));
    return a;
}

__device__ __forceinline__ void ldmatrix_x4(uint32_t* r, uint32_t addr) {
    asm volatile("ldmatrix.sync.aligned.m8n8.x4.shared.b16 {%0,%1,%2,%3}, [%4];"
                 : "=r"(r[0]), "=r"(r[1]), "=r"(r[2]), "=r"(r[3]) : "r"(addr));
}

__device__ __forceinline__ void mma_bf16(float* c, const uint32_t* a, uint32_t b0, uint32_t b1) {
    asm volatile(
        "mma.sync.aligned.m16n8k16.row.col.f32.bf16.bf16.f32 "
        "{%0,%1,%2,%3}, {%4,%5,%6,%7}, {%8,%9}, {%0,%1,%2,%3};"
        : "+f"(c[0]), "+f"(c[1]), "+f"(c[2]), "+f"(c[3])
        : "r"(a[0]), "r"(a[1]), "r"(a[2]), "r"(a[3]), "r"(b0), "r"(b1));
}

__device__ __forceinline__ void cp16(uint32_t dst, const void* src, uint32_t srcsize) {
    asm volatile("cp.async.cg.shared.global [%0], [%1], 16, %2;"
                 :: "r"(dst), "l"(src), "r"(srcsize) : "memory");
}
#define CP_COMMIT() asm volatile("cp.async.commit_group;" ::: "memory")
#define CP_WAIT1()  asm volatile("cp.async.wait_group 1;" ::: "memory")
#define CP_WAIT0()  asm volatile("cp.async.wait_group 0;" ::: "memory")

__device__ __forceinline__ void split_bf16(float v, __nv_bfloat16& hi, __nv_bfloat16& lo) {
    hi = __float2bfloat16_rn(v);
    lo = __float2bfloat16_rn(v - __bfloat162float(hi));
}

// ---------------- SMEM layout (dynamic), BK=16, stride-48 rows --------------
// per stage: A_hi[64*48] A_lo[64*48] B_hi[256*48] B_lo[256*48] = 30720 B
#define A_HI 0
#define A_LO 3072
#define B_HI 6144
#define B_LO 18432
#define STAGE_STRIDE 30720
#define P_CB  92160
#define P_LG  93184
#define P_LB  94208
#define P_LW  95232
#define S_SUM 96256
#define S_SQ  96768
#define S_DOT 97280
#define CONV_SMEM 97792

// ---------------- merged pack: w1, w2 (split bf16) and x (split bf16) -------
__global__ void pack_all_kernel(const float* __restrict__ w1, const float* __restrict__ w2,
                                const float* __restrict__ x,
                                __nv_bfloat16* __restrict__ w1h, __nv_bfloat16* __restrict__ w1l,
                                __nv_bfloat16* __restrict__ w2h, __nv_bfloat16* __restrict__ w2l,
                                __nv_bfloat16* __restrict__ xh, __nv_bfloat16* __restrict__ xl) {
    int bid = blockIdx.x;
    if (bid < 2 * KTOT) {
        const float* w = (bid < KTOT) ? w1 : w2;
        __nv_bfloat16* wh = (bid < KTOT) ? w1h : w2h;
        __nv_bfloat16* wl = (bid < KTOT) ? w1l : w2l;
        int o = (bid % KTOT) * 256 + threadIdx.x;
        int f = o / KTOT;
        int rem = o - f * KTOT;
        int tap = rem >> 8;
        int d = rem & 255;
        float v = w[(f * DD + d) * 3 + tap];
        __nv_bfloat16 hi, lo;
        split_bf16(v, hi, lo);
        wh[o] = hi; wl[o] = lo;
    } else {
        int o = ((bid - 2 * KTOT) * 256 + threadIdx.x) * 4;
        float4 v = *(const float4*)(x + o);
        __nv_bfloat16 h[4], l[4];
        split_bf16(v.x, h[0], l[0]); split_bf16(v.y, h[1], l[1]);
        split_bf16(v.z, h[2], l[2]); split_bf16(v.w, h[3], l[3]);
        *(uint2*)(xh + o) = *(uint2*)h;
        *(uint2*)(xl + o) = *(uint2*)l;
    }
}

// ---------------- conv+bias+LN+ReLU: BM=64 x BN=256, BK=16, 2 CTAs/SM -------
// 256 threads, 8 warps (4m x 2n), warp tile 16x128, 3-stage cp.async pipeline,
// one __syncthreads per chunk. bf16 3-term split, fp32 accum.
template <bool OUT_SPLIT>
__global__ void __launch_bounds__(256, 2)
conv_pipe_kernel(const __nv_bfloat16* __restrict__ inh,
                 const __nv_bfloat16* __restrict__ inl,
                 const __nv_bfloat16* __restrict__ wph,
                 const __nv_bfloat16* __restrict__ wpl,
                 const float* __restrict__ cb, const float* __restrict__ lg,
                 const float* __restrict__ lb, const float* __restrict__ lw,
                 const float* __restrict__ lbias,
                 __nv_bfloat16* __restrict__ outh, __nv_bfloat16* __restrict__ outl,
                 float* __restrict__ dur) {
    extern __shared__ char smem[];
    const uint32_t sb = smem_u32(smem);
    const int tid = threadIdx.x;
    const int warp = tid >> 5, lane = tid & 31;
    const int wm = warp & 3, wn = warp >> 2;      // 4m x 2n
    const int m0 = blockIdx.x * 64;

    ((float*)(smem + P_CB))[tid] = cb[tid];
    ((float*)(smem + P_LG))[tid] = lg[tid];
    ((float*)(smem + P_LB))[tid] = lb[tid];
    ((float*)(smem + P_LW))[tid] = lw[tid];

    float acc[16][4];
#pragma unroll
    for (int j = 0; j < 16; ++j)
#pragma unroll
        for (int e = 0; e < 4; ++e) acc[j][e] = 0.f;

    // A-load geometry: threads 0..127 -> A_hi, 128..255 -> A_lo
    const int arow = (tid & 127) >> 1;   // 0..63
    const int aq   = tid & 1;            // 16B unit in 32B row
    const int am = m0 + arow;
    const int at = am & (TT - 1);
    const bool alo = tid >= 128;

    auto load_stage = [&](int ch) {
        const uint32_t base = sb + (uint32_t)((ch % 3) * STAGE_STRIDE);
        const int kk0 = ch * 16;
        const int tap = kk0 >> 8;
        const int d0  = kk0 & 255;
        const int dt  = tap - 1;
        // A: one 16B unit per thread
        {
            int tt = at + dt;
            uint32_t ok = (tt >= 0 && tt < TT) ? 16u : 0u;
            int ttc = min(max(tt, 0), TT - 1);
            size_t goff = (size_t)(am - at + ttc) * DD + d0 + aq * 8;
            uint32_t soff = (uint32_t)(arow * 48 + aq * 16);
            cp16(base + (alo ? A_LO : A_HI) + soff, (alo ? inl : inh) + goff, ok);
        }
        // B: 256 rows x 2 units x {hi,lo} = 1024 units -> 4 per thread
#pragma unroll
        for (int p = 0; p < 4; ++p) {
            int idx = tid + p * 256;
            int half = idx >> 9;           // 0=hi, 1=lo
            int rem = idx & 511;
            int row = rem >> 1;
            int q = rem & 1;
            size_t goff = (size_t)row * KTOT + kk0 + q * 8;
            uint32_t soff = (uint32_t)(row * 48 + q * 16);
            cp16(base + (half ? B_LO : B_HI) + soff, (half ? wpl : wph) + goff, 16u);
        }
        CP_COMMIT();
    };

    // fragment smem offsets (within stage)
    const uint32_t a_off = (uint32_t)((wm * 16 + (lane & 15)) * 48 + ((lane >> 4) & 1) * 16);
    uint32_t b_off[8];
#pragma unroll
    for (int jp = 0; jp < 8; ++jp)
        b_off[jp] = (uint32_t)((wn * 128 + jp * 16 + (lane & 7) + ((lane >> 4) & 1) * 8) * 48 +
                               ((lane >> 3) & 1) * 16);

    load_stage(0);
    load_stage(1);

    for (int ch = 0; ch < 48; ++ch) {
        if (ch < 47) { CP_WAIT1(); } else { CP_WAIT0(); }
        __syncthreads();                   // stage ch visible; chunk ch-1 drained
        if (ch + 2 < 48) load_stage(ch + 2);   // writes buffer (ch-1)%3 — safe

        const uint32_t base = sb + (uint32_t)((ch % 3) * STAGE_STRIDE);
        uint32_t ah[4], al[4];
        ldmatrix_x4(ah, base + A_HI + a_off);
        ldmatrix_x4(al, base + A_LO + a_off);
#pragma unroll
        for (int jp = 0; jp < 8; ++jp) {
            uint32_t bh[4], bl[4];
            ldmatrix_x4(bh, base + B_HI + b_off[jp]);
            ldmatrix_x4(bl, base + B_LO + b_off[jp]);
            mma_bf16(acc[jp * 2],     ah, bh[0], bh[1]);
            mma_bf16(acc[jp * 2 + 1], ah, bh[2], bh[3]);
            mma_bf16(acc[jp * 2],     ah, bl[0], bl[1]);
            mma_bf16(acc[jp * 2 + 1], ah, bl[2], bl[3]);
            mma_bf16(acc[jp * 2],     al, bh[0], bh[1]);
            mma_bf16(acc[jp * 2 + 1], al, bh[2], bh[3]);
        }
    }
    __syncthreads();

    // ---------------- epilogue: +bias, LayerNorm(256), ReLU -----------------
    const float* scb = (const float*)(smem + P_CB);
    const float* slg = (const float*)(smem + P_LG);
    const float* slb = (const float*)(smem + P_LB);
    const float* slw = (const float*)(smem + P_LW);
    float* ssum = (float*)(smem + S_SUM);   // [2][64]
    float* ssq  = (float*)(smem + S_SQ);
    float* sdot = (float*)(smem + S_DOT);

    float s0 = 0.f, q0 = 0.f, s1 = 0.f, q1 = 0.f;
#pragma unroll
    for (int j = 0; j < 16; ++j) {
        int cj = wn * 128 + j * 8 + (lane & 3) * 2;
        float b0v = scb[cj], b1v = scb[cj + 1];
        acc[j][0] += b0v; acc[j][1] += b1v;
        acc[j][2] += b0v; acc[j][3] += b1v;
        s0 += acc[j][0] + acc[j][1];
        q0 += acc[j][0] * acc[j][0] + acc[j][1] * acc[j][1];
        s1 += acc[j][2] + acc[j][3];
        q1 += acc[j][2] * acc[j][2] + acc[j][3] * acc[j][3];
    }
#pragma unroll
    for (int off = 1; off <= 2; off <<= 1) {
        s0 += __shfl_xor_sync(0xffffffffu, s0, off);
        q0 += __shfl_xor_sync(0xffffffffu, q0, off);
        s1 += __shfl_xor_sync(0xffffffffu, s1, off);
        q1 += __shfl_xor_sync(0xffffffffu, q1, off);
    }
    const int r0 = wm * 16 + (lane >> 2);
    if ((lane & 3) == 0) {
        ssum[wn * 64 + r0] = s0;  ssum[wn * 64 + r0 + 8] = s1;
        ssq[wn * 64 + r0]  = q0;  ssq[wn * 64 + r0 + 8]  = q1;
    }
    __syncthreads();
    float S0 = ssum[r0] + ssum[64 + r0];
    float Q0 = ssq[r0]  + ssq[64 + r0];
    float S1 = ssum[r0 + 8] + ssum[64 + r0 + 8];
    float Q1 = ssq[r0 + 8]  + ssq[64 + r0 + 8];
    float mu0 = S0 * (1.f / 256.f), mu1 = S1 * (1.f / 256.f);
    float rs0 = rsqrtf(Q0 * (1.f / 256.f) - mu0 * mu0 + 1e-5f);
    float rs1 = rsqrtf(Q1 * (1.f / 256.f) - mu1 * mu1 + 1e-5f);

    float dot0 = 0.f, dot1 = 0.f;
#pragma unroll
    for (int j = 0; j < 16; ++j) {
        int cj = wn * 128 + j * 8 + (lane & 3) * 2;
        float g0 = slg[cj], g1 = slg[cj + 1], d0v = slb[cj], d1v = slb[cj + 1];
        float v0 = fmaxf(fmaf((acc[j][0] - mu0) * rs0, g0, d0v), 0.f);
        float v1 = fmaxf(fmaf((acc[j][1] - mu0) * rs0, g1, d1v), 0.f);
        float v2 = fmaxf(fmaf((acc[j][2] - mu1) * rs1, g0, d0v), 0.f);
        float v3 = fmaxf(fmaf((acc[j][3] - mu1) * rs1, g1, d1v), 0.f);
        if (OUT_SPLIT) {
            __nv_bfloat16 h0, l0, h1, l1;
            size_t i0 = (size_t)(m0 + r0) * FF + cj;
            size_t i1 = (size_t)(m0 + r0 + 8) * FF + cj;
            split_bf16(v0, h0, l0); split_bf16(v1, h1, l1);
            *(__nv_bfloat162*)(outh + i0) = __nv_bfloat162(h0, h1);
            *(__nv_bfloat162*)(outl + i0) = __nv_bfloat162(l0, l1);
            split_bf16(v2, h0, l0); split_bf16(v3, h1, l1);
            *(__nv_bfloat162*)(outh + i1) = __nv_bfloat162(h0, h1);
            *(__nv_bfloat162*)(outl + i1) = __nv_bfloat162(l0, l1);
        } else {
            float w0 = slw[cj], w1 = slw[cj + 1];
            dot0 = fmaf(v0, w0, fmaf(v1, w1, dot0));
            dot1 = fmaf(v2, w0, fmaf(v3, w1, dot1));
        }
    }
    if (!OUT_SPLIT) {
#pragma unroll
        for (int off = 1; off <= 2; off <<= 1) {
            dot0 += __shfl_xor_sync(0xffffffffu, dot0, off);
            dot1 += __shfl_xor_sync(0xffffffffu, dot1, off);
        }
        if ((lane & 3) == 0) {
            sdot[wn * 64 + r0] = dot0;
            sdot[wn * 64 + r0 + 8] = dot1;
        }
        __syncthreads();
        if (tid < 64)
            dur[m0 + tid] = fmaxf(sdot[tid] + sdot[64 + tid] + lbias[0], 0.f);
    }
}

// ---------------- cumsum: one block, warp per batch --------------------------
__global__ void cumsum_kernel(const int* __restrict__ target, int* __restrict__ cum) {
    int w = threadIdx.x >> 5;     // batch
    int l = threadIdx.x & 31;
    const int* src = target + w * TT;
    int* dst = cum + w * TT;
    int v[16];
    int s = 0;
#pragma unroll
    for (int i = 0; i < 16; ++i) { v[i] = src[l * 16 + i]; s += v[i]; }
    int p = s;
#pragma unroll
    for (int off = 1; off < 32; off <<= 1) {
        int u = __shfl_up_sync(0xffffffffu, p, off);
        if (l >= off) p += u;
    }
    int run = p - s;
#pragma unroll
    for (int i = 0; i < 16; ++i) { run += v[i]; dst[l * 16 + i] = run; }
}

// ---------------- length-regulator gather (8 rows per block) -----------------
__global__ void gather_kernel(const float* __restrict__ x, const int* __restrict__ cum,
                              float* __restrict__ out) {
    __shared__ int sc[TT];
    int b = blockIdx.y;
    for (int i = threadIdx.x; i < TT; i += 256) sc[i] = cum[b * TT + i];
    __syncthreads();
    int total = sc[TT - 1];
    int lane = threadIdx.x & 63;
#pragma unroll
    for (int r = 0; r < 2; ++r) {
        int t_out = blockIdx.x * 8 + r * 4 + (threadIdx.x >> 6);
        int lo = 0, hi = TT;
        while (lo < hi) {
            int mid = (lo + hi) >> 1;
            if (sc[mid] <= t_out) lo = mid + 1; else hi = mid;
        }
        int idx = min(lo, TT - 1);
        bool valid = t_out < total;
        float4 v = make_float4(0.f, 0.f, 0.f, 0.f);
        if (valid)
            v = ((const float4*)(x + ((size_t)(b * TT + idx)) * DD))[lane];
        ((float4*)(out + ((size_t)(b * MEL + t_out)) * DD))[lane] = v;
    }
}

// ---------------- launch ----------------------------------------------------
extern "C" void kernel_launch(void* const* d_in, const int* in_sizes, int n_in,
                              void* d_out, int out_size) {
    const float* x       = (const float*)d_in[0];
    const int*   target  = (const int*)d_in[1];
    const float* conv1_w = (const float*)d_in[3];
    const float* conv1_b = (const float*)d_in[4];
    const float* ln1_g   = (const float*)d_in[5];
    const float* ln1_b   = (const float*)d_in[6];
    const float* conv2_w = (const float*)d_in[7];
    const float* conv2_b = (const float*)d_in[8];
    const float* ln2_g   = (const float*)d_in[9];
    const float* ln2_b   = (const float*)d_in[10];
    const float* lin_w   = (const float*)d_in[11];
    const float* lin_b   = (const float*)d_in[12];

    float* out_gather = (float*)d_out;
    float* out_dur    = (float*)d_out + OUT_GATHER_ELEMS;

    __nv_bfloat16 *w1h, *w1l, *w2h, *w2l, *xh, *xl, *h1h, *h1l;
    int* cum;
    cudaGetSymbolAddress((void**)&w1h, g_w1h);
    cudaGetSymbolAddress((void**)&w1l, g_w1l);
    cudaGetSymbolAddress((void**)&w2h, g_w2h);
    cudaGetSymbolAddress((void**)&w2l, g_w2l);
    cudaGetSymbolAddress((void**)&xh,  g_xh);
    cudaGetSymbolAddress((void**)&xl,  g_xl);
    cudaGetSymbolAddress((void**)&h1h, g_h1h);
    cudaGetSymbolAddress((void**)&h1l, g_h1l);
    cudaGetSymbolAddress((void**)&cum, g_cum);

    cudaFuncSetAttribute(conv_pipe_kernel<true>,
                         cudaFuncAttributeMaxDynamicSharedMemorySize, CONV_SMEM);
    cudaFuncSetAttribute(conv_pipe_kernel<false>,
                         cudaFuncAttributeMaxDynamicSharedMemorySize, CONV_SMEM);

    pack_all_kernel<<<2 * KTOT + MM * DD / 1024, 256>>>(
        conv1_w, conv2_w, x, w1h, w1l, w2h, w2l, xh, xl);
    cumsum_kernel<<<1, 1024>>>(target, cum);

    conv_pipe_kernel<true><<<MM / 64, 256, CONV_SMEM>>>(
        xh, xl, w1h, w1l,
        conv1_b, ln1_g, ln1_b, lin_w, lin_b, h1h, h1l, nullptr);

    conv_pipe_kernel<false><<<MM / 64, 256, CONV_SMEM>>>(
        h1h, h1l, w2h, w2l,
        conv2_b, ln2_g, ln2_b, lin_w, lin_b, nullptr, nullptr, out_dur);

    gather_kernel<<<dim3(MEL / 8, BB), 256>>>(x, cum, out_gather);
}

// round 11
// speedup vs baseline: 1.3844x; 1.3844x over previous
#include <cuda_runtime.h>
#include <cuda_bf16.h>
#include <cstdint>

#define BB 32
#define TT 512
#define DD 256
#define FF 256
#define MM (BB * TT)          // 16384
#define KTOT 768
#define MEL 2304
#define NCH 24                // K chunks of 32
#define OUT_GATHER_ELEMS (BB * MEL * DD)   // 18874368

// ---------------- device scratch (no allocs allowed) ----------------
// packed weights: per chunk 32KB = [hi 16KB][lo 16KB], each SW64-swizzled
__device__ __nv_bfloat16 g_w1p[NCH * 16384];   // 24*32768 bytes
__device__ __nv_bfloat16 g_w2p[NCH * 16384];
__device__ __nv_bfloat16 g_xh[MM * DD];
__device__ __nv_bfloat16 g_xl[MM * DD];
__device__ __nv_bfloat16 g_h1h[MM * FF];
__device__ __nv_bfloat16 g_h1l[MM * FF];
__device__ int g_cum[BB * TT];

// ---------------- helpers ----------------
__device__ __forceinline__ uint32_t smem_u32(const void* p) {
    uint32_t a;
    asm("{ .reg .u64 t; cvta.to.shared.u64 t, %1; cvt.u32.u64 %0, t; }" : "=r"(a) : "l"(p));
    return a;
}
#define SW64(o) ((o) ^ (((o) >> 3) & 0x30))

__device__ __forceinline__ void ldmatrix_x4(uint32_t* r, uint32_t addr) {
    asm volatile("ldmatrix.sync.aligned.m8n8.x4.shared.b16 {%0,%1,%2,%3}, [%4];"
                 : "=r"(r[0]), "=r"(r[1]), "=r"(r[2]), "=r"(r[3]) : "r"(addr));
}

__device__ __forceinline__ void mma_bf16(float* c, const uint32_t* a, uint32_t b0, uint32_t b1) {
    asm volatile(
        "mma.sync.aligned.m16n8k16.row.col.f32.bf16.bf16.f32 "
        "{%0,%1,%2,%3}, {%4,%5,%6,%7}, {%8,%9}, {%0,%1,%2,%3};"
        : "+f"(c[0]), "+f"(c[1]), "+f"(c[2]), "+f"(c[3])
        : "r"(a[0]), "r"(a[1]), "r"(a[2]), "r"(a[3]), "r"(b0), "r"(b1));
}

__device__ __forceinline__ void cp16(uint32_t dst, const void* src, uint32_t srcsize) {
    asm volatile("cp.async.cg.shared.global [%0], [%1], 16, %2;"
                 :: "r"(dst), "l"(src), "r"(srcsize) : "memory");
}
#define CP_COMMIT()  asm volatile("cp.async.commit_group;" ::: "memory")
#define CP_WAITG(n)  asm volatile("cp.async.wait_group %0;" :: "n"(n) : "memory")

__device__ __forceinline__ void bulk_cp(uint32_t dst, const void* src, uint32_t bytes,
                                        uint32_t mbar) {
    asm volatile(
        "cp.async.bulk.shared::cta.global.mbarrier::complete_tx::bytes [%0], [%1], %2, [%3];"
        :: "r"(dst), "l"(src), "r"(bytes), "r"(mbar) : "memory");
}
#define MBAR_INIT(mb, n) \
    asm volatile("mbarrier.init.shared.b64 [%0], %1;" :: "r"(mb), "r"(n) : "memory")
#define MBAR_EXPECT(mb, tx) \
    asm volatile("mbarrier.arrive.expect_tx.shared.b64 _, [%0], %1;" :: "r"(mb), "r"(tx) : "memory")
#define MBAR_WAIT(mb, par) do {                                               \
    uint32_t _mb = (mb); uint32_t _p = (par); uint32_t _done;                 \
    asm volatile("{\n\t.reg .pred p;\n\t"                                     \
        "mbarrier.try_wait.parity.acquire.cta.shared::cta.b64 p, [%1], %2;\n\t" \
        "selp.b32 %0, 1, 0, p;\n\t}"                                          \
        : "=r"(_done) : "r"(_mb), "r"(_p) : "memory");                        \
    if (!_done) {                                                             \
        asm volatile("{\n\t.reg .pred P1;\n\t"                                \
            "WL_%=:\n\t"                                                      \
            "mbarrier.try_wait.parity.acquire.cta.shared::cta.b64 P1, [%0], %1, 0x989680;\n\t" \
            "@P1 bra.uni WD_%=;\n\tbra.uni WL_%=;\n\tWD_%=:\n\t}"             \
            :: "r"(_mb), "r"(_p) : "memory");                                 \
    }                                                                         \
} while (0)

__device__ __forceinline__ void split_bf16(float v, __nv_bfloat16& hi, __nv_bfloat16& lo) {
    hi = __float2bfloat16_rn(v);
    lo = __float2bfloat16_rn(v - __bfloat162float(hi));
}

// ---------------- SMEM layout (dynamic) ----------------
// per stage: A_hi[128*80] A_lo[128*80] B[32768 SW64 blocks hi|lo] = 53248 B
#define A_HI 0
#define A_LO 10240
#define B_BLK 20480
#define STAGE_STRIDE 53248
#define P_CB   212992
#define P_LG   214016
#define P_LB   215040
#define P_LW   216064
#define S_SUM  217088
#define S_SQ   219136
#define S_DOT  221184
#define SM_MBAR 223232
#define CONV_SMEM 223296

// ---------------- merged pack: w1, w2 (SW64 chunk blocks) + x split ---------
__global__ void pack_all_kernel(const float* __restrict__ w1, const float* __restrict__ w2,
                                const float* __restrict__ x,
                                __nv_bfloat16* __restrict__ w1p, __nv_bfloat16* __restrict__ w2p,
                                __nv_bfloat16* __restrict__ xh, __nv_bfloat16* __restrict__ xl) {
    int bid = blockIdx.x;
    if (bid < 2 * KTOT) {
        const float* w = (bid < KTOT) ? w1 : w2;
        __nv_bfloat16* wp = (bid < KTOT) ? w1p : w2p;
        int o = (bid % KTOT) * 256 + threadIdx.x;   // (f, kk) flat
        int f = o / KTOT;
        int rem = o - f * KTOT;
        int tap = rem >> 8;
        int d = rem & 255;
        int kk = tap * 256 + d;
        float v = w[(f * DD + d) * 3 + tap];
        __nv_bfloat16 hi, lo;
        split_bf16(v, hi, lo);
        int ch = kk >> 5;
        int inner = kk & 31;
        uint32_t sw = SW64((uint32_t)(f * 64 + inner * 2));   // byte off in 16KB block
        wp[ch * 16384 + (sw >> 1)] = hi;
        wp[ch * 16384 + 8192 + (sw >> 1)] = lo;
    } else {
        int o = ((bid - 2 * KTOT) * 256 + threadIdx.x) * 4;
        float4 v = *(const float4*)(x + o);
        __nv_bfloat16 h[4], l[4];
        split_bf16(v.x, h[0], l[0]); split_bf16(v.y, h[1], l[1]);
        split_bf16(v.z, h[2], l[2]); split_bf16(v.w, h[3], l[3]);
        *(uint2*)(xh + o) = *(uint2*)h;
        *(uint2*)(xl + o) = *(uint2*)l;
    }
}

// ---------------- conv+bias+LN+ReLU: BM=128 x BN=256, BK=32 -----------------
// 512 threads (4m x 4n warps, warp tile 32x64), 4-stage pipeline:
// A via cp.async (cp16), B via ONE cp.async.bulk per stage (pre-swizzled SW64),
// one __syncthreads per chunk. bf16 3-term split, fp32 accum.
template <bool OUT_SPLIT>
__global__ void __launch_bounds__(512, 1)
conv_pipe_kernel(const __nv_bfloat16* __restrict__ inh,
                 const __nv_bfloat16* __restrict__ inl,
                 const __nv_bfloat16* __restrict__ wp,
                 const float* __restrict__ cb, const float* __restrict__ lg,
                 const float* __restrict__ lb, const float* __restrict__ lw,
                 const float* __restrict__ lbias,
                 __nv_bfloat16* __restrict__ outh, __nv_bfloat16* __restrict__ outl,
                 float* __restrict__ dur) {
    extern __shared__ char smem[];
    const uint32_t sb = smem_u32(smem);
    const int tid = threadIdx.x;
    const int warp = tid >> 5, lane = tid & 31;
    const int wm = warp & 3, wn = warp >> 2;      // 4m x 4n
    const int m0 = blockIdx.x * 128;

    if (tid < 256) {
        ((float*)(smem + P_CB))[tid] = cb[tid];
        ((float*)(smem + P_LG))[tid] = lg[tid];
        ((float*)(smem + P_LB))[tid] = lb[tid];
        ((float*)(smem + P_LW))[tid] = lw[tid];
    }
    if (tid == 0) {
#pragma unroll
        for (int i = 0; i < 4; ++i) MBAR_INIT(sb + SM_MBAR + i * 8, 1);
    }
    __syncthreads();

    float acc[2][8][4];
#pragma unroll
    for (int mi = 0; mi < 2; ++mi)
#pragma unroll
        for (int j = 0; j < 8; ++j)
#pragma unroll
            for (int e = 0; e < 4; ++e) acc[mi][j][e] = 0.f;

    const int lrow = tid >> 2;     // 0..127
    const int lq   = tid & 3;      // 16B unit within 64B payload
    const int am = m0 + lrow;
    const int at = am & (TT - 1);

    auto load_stage = [&](int ch) {
        const uint32_t base = sb + (uint32_t)((ch & 3) * STAGE_STRIDE);
        const int kk0 = ch * 32;
        const int tap = kk0 >> 8;
        const int d0  = kk0 & 255;
        const int dt  = tap - 1;
        {   // A: 2 cp16 per thread
            int tt = at + dt;
            uint32_t ok = (tt >= 0 && tt < TT) ? 16u : 0u;
            int ttc = min(max(tt, 0), TT - 1);
            size_t goff = (size_t)(am - at + ttc) * DD + d0 + lq * 8;
            uint32_t soff = (uint32_t)(lrow * 80 + lq * 16);
            cp16(base + A_HI + soff, inh + goff, ok);
            cp16(base + A_LO + soff, inl + goff, ok);
        }
        CP_COMMIT();
        if (tid == 0) {   // B: one 32KB bulk copy, tracked by stage mbarrier
            uint32_t mb = sb + SM_MBAR + (ch & 3) * 8;
            MBAR_EXPECT(mb, 32768u);
            bulk_cp(base + B_BLK, (const char*)wp + (size_t)ch * 32768, 32768u, mb);
        }
    };

    // fragment smem offsets
    uint32_t a_off[2];
#pragma unroll
    for (int mi = 0; mi < 2; ++mi)
        a_off[mi] = (uint32_t)((wm * 32 + mi * 16 + (lane & 15)) * 80 + ((lane >> 4) & 1) * 16);
    // B unswizzled base offsets (within 16KB block); swizzle applied per use
    uint32_t b_base[4];
#pragma unroll
    for (int jp = 0; jp < 4; ++jp) {
        int row = wn * 64 + jp * 16 + (lane & 7) + ((lane >> 4) & 1) * 8;
        b_base[jp] = (uint32_t)(row * 64 + ((lane >> 3) & 1) * 16);
    }

    load_stage(0);
    load_stage(1);
    load_stage(2);

    for (int ch = 0; ch < NCH; ++ch) {
        if (ch <= NCH - 3)      { CP_WAITG(2); }
        else if (ch == NCH - 2) { CP_WAITG(1); }
        else                    { CP_WAITG(0); }
        MBAR_WAIT(sb + SM_MBAR + (ch & 3) * 8, (ch >> 2) & 1);
        __syncthreads();                       // stage ch visible; chunk ch-1 drained
        if (ch + 3 < NCH) load_stage(ch + 3);  // writes buffer (ch-1)&3 — safe

        const uint32_t base = sb + (uint32_t)((ch & 3) * STAGE_STRIDE);
        const uint32_t bh_base = base + B_BLK;
#pragma unroll
        for (int s = 0; s < 2; ++s) {
            uint32_t ah[2][4], al[2][4];
#pragma unroll
            for (int mi = 0; mi < 2; ++mi) {
                ldmatrix_x4(ah[mi], base + A_HI + a_off[mi] + s * 32);
                ldmatrix_x4(al[mi], base + A_LO + a_off[mi] + s * 32);
            }
#pragma unroll
            for (int jp = 0; jp < 4; ++jp) {
                uint32_t sw = SW64(b_base[jp] + s * 32);
                uint32_t bh[4], bl[4];
                ldmatrix_x4(bh, bh_base + sw);
                ldmatrix_x4(bl, bh_base + 16384 + sw);
#pragma unroll
                for (int mi = 0; mi < 2; ++mi) {
                    mma_bf16(acc[mi][jp * 2],     ah[mi], bh[0], bh[1]);
                    mma_bf16(acc[mi][jp * 2 + 1], ah[mi], bh[2], bh[3]);
                    mma_bf16(acc[mi][jp * 2],     ah[mi], bl[0], bl[1]);
                    mma_bf16(acc[mi][jp * 2 + 1], ah[mi], bl[2], bl[3]);
                    mma_bf16(acc[mi][jp * 2],     al[mi], bh[0], bh[1]);
                    mma_bf16(acc[mi][jp * 2 + 1], al[mi], bh[2], bh[3]);
                }
            }
        }
    }
    __syncthreads();

    // ---------------- epilogue: +bias, LayerNorm(256), ReLU -----------------
    const float* scb = (const float*)(smem + P_CB);
    const float* slg = (const float*)(smem + P_LG);
    const float* slb = (const float*)(smem + P_LB);
    const float* slw = (const float*)(smem + P_LW);
    float* ssum = (float*)(smem + S_SUM);   // [4][128]
    float* ssq  = (float*)(smem + S_SQ);
    float* sdot = (float*)(smem + S_DOT);

    float ps[2][2], pq[2][2];
#pragma unroll
    for (int mi = 0; mi < 2; ++mi)
#pragma unroll
        for (int h = 0; h < 2; ++h) { ps[mi][h] = 0.f; pq[mi][h] = 0.f; }

#pragma unroll
    for (int mi = 0; mi < 2; ++mi)
#pragma unroll
        for (int j = 0; j < 8; ++j) {
            int cj = wn * 64 + (j >> 1) * 16 + (j & 1) * 8 + (lane & 3) * 2;
            float b0v = scb[cj], b1v = scb[cj + 1];
            float v0 = acc[mi][j][0] + b0v, v1 = acc[mi][j][1] + b1v;
            float v2 = acc[mi][j][2] + b0v, v3 = acc[mi][j][3] + b1v;
            acc[mi][j][0] = v0; acc[mi][j][1] = v1;
            acc[mi][j][2] = v2; acc[mi][j][3] = v3;
            ps[mi][0] += v0 + v1; pq[mi][0] += v0 * v0 + v1 * v1;
            ps[mi][1] += v2 + v3; pq[mi][1] += v2 * v2 + v3 * v3;
        }
#pragma unroll
    for (int off = 1; off <= 2; off <<= 1)
#pragma unroll
        for (int mi = 0; mi < 2; ++mi)
#pragma unroll
            for (int h = 0; h < 2; ++h) {
                ps[mi][h] += __shfl_xor_sync(0xffffffffu, ps[mi][h], off);
                pq[mi][h] += __shfl_xor_sync(0xffffffffu, pq[mi][h], off);
            }
    const int rbase = wm * 32 + (lane >> 2);
    if ((lane & 3) == 0) {
#pragma unroll
        for (int mi = 0; mi < 2; ++mi)
#pragma unroll
            for (int h = 0; h < 2; ++h) {
                int r = rbase + mi * 16 + h * 8;
                ssum[wn * 128 + r] = ps[mi][h];
                ssq[wn * 128 + r]  = pq[mi][h];
            }
    }
    __syncthreads();

    float dot[2][2] = {{0.f, 0.f}, {0.f, 0.f}};
#pragma unroll
    for (int mi = 0; mi < 2; ++mi)
#pragma unroll
        for (int h = 0; h < 2; ++h) {
            int r = rbase + mi * 16 + h * 8;
            float S = ssum[r] + ssum[128 + r] + ssum[256 + r] + ssum[384 + r];
            float Q = ssq[r]  + ssq[128 + r]  + ssq[256 + r]  + ssq[384 + r];
            float mu = S * (1.f / 256.f);
            float rs = rsqrtf(Q * (1.f / 256.f) - mu * mu + 1e-5f);
#pragma unroll
            for (int j = 0; j < 8; ++j) {
                int cj = wn * 64 + (j >> 1) * 16 + (j & 1) * 8 + (lane & 3) * 2;
                float g0 = slg[cj], g1 = slg[cj + 1];
                float d0v = slb[cj], d1v = slb[cj + 1];
                float v0 = fmaxf(fmaf((acc[mi][j][h * 2]     - mu) * rs, g0, d0v), 0.f);
                float v1 = fmaxf(fmaf((acc[mi][j][h * 2 + 1] - mu) * rs, g1, d1v), 0.f);
                if (OUT_SPLIT) {
                    __nv_bfloat16 h0, l0, h1, l1;
                    split_bf16(v0, h0, l0); split_bf16(v1, h1, l1);
                    size_t idx = (size_t)(m0 + r) * FF + cj;
                    *(__nv_bfloat162*)(outh + idx) = __nv_bfloat162(h0, h1);
                    *(__nv_bfloat162*)(outl + idx) = __nv_bfloat162(l0, l1);
                } else {
                    dot[mi][h] = fmaf(v0, slw[cj], fmaf(v1, slw[cj + 1], dot[mi][h]));
                }
            }
        }
    if (!OUT_SPLIT) {
#pragma unroll
        for (int off = 1; off <= 2; off <<= 1)
#pragma unroll
            for (int mi = 0; mi < 2; ++mi)
#pragma unroll
                for (int h = 0; h < 2; ++h)
                    dot[mi][h] += __shfl_xor_sync(0xffffffffu, dot[mi][h], off);
        if ((lane & 3) == 0) {
#pragma unroll
            for (int mi = 0; mi < 2; ++mi)
#pragma unroll
                for (int h = 0; h < 2; ++h) {
                    int r = rbase + mi * 16 + h * 8;
                    sdot[wn * 128 + r] = dot[mi][h];
                }
        }
        __syncthreads();
        if (tid < 128)
            dur[m0 + tid] = fmaxf(sdot[tid] + sdot[128 + tid] + sdot[256 + tid] +
                                  sdot[384 + tid] + lbias[0], 0.f);
    }
}

// ---------------- cumsum: one block, warp per batch --------------------------
__global__ void cumsum_kernel(const int* __restrict__ target, int* __restrict__ cum) {
    int w = threadIdx.x >> 5;
    int l = threadIdx.x & 31;
    const int* src = target + w * TT;
    int* dst = cum + w * TT;
    int v[16];
    int s = 0;
#pragma unroll
    for (int i = 0; i < 16; ++i) { v[i] = src[l * 16 + i]; s += v[i]; }
    int p = s;
#pragma unroll
    for (int off = 1; off < 32; off <<= 1) {
        int u = __shfl_up_sync(0xffffffffu, p, off);
        if (l >= off) p += u;
    }
    int run = p - s;
#pragma unroll
    for (int i = 0; i < 16; ++i) { run += v[i]; dst[l * 16 + i] = run; }
}

// ---------------- length-regulator gather -----------------------------------
__global__ void gather_kernel(const float* __restrict__ x, const int* __restrict__ cum,
                              float* __restrict__ out) {
    __shared__ int sc[TT];
    int b = blockIdx.y;
    for (int i = threadIdx.x; i < TT; i += 256) sc[i] = cum[b * TT + i];
    __syncthreads();
    int total = sc[TT - 1];
    int t_out = blockIdx.x * 4 + (threadIdx.x >> 6);
    int lane  = threadIdx.x & 63;
    int lo = 0, hi = TT;
    while (lo < hi) {
        int mid = (lo + hi) >> 1;
        if (sc[mid] <= t_out) lo = mid + 1; else hi = mid;
    }
    int idx = min(lo, TT - 1);
    bool valid = t_out < total;
    float4 v = make_float4(0.f, 0.f, 0.f, 0.f);
    if (valid)
        v = ((const float4*)(x + ((size_t)(b * TT + idx)) * DD))[lane];
    ((float4*)(out + ((size_t)(b * MEL + t_out)) * DD))[lane] = v;
}

// ---------------- launch ----------------------------------------------------
extern "C" void kernel_launch(void* const* d_in, const int* in_sizes, int n_in,
                              void* d_out, int out_size) {
    const float* x       = (const float*)d_in[0];
    const int*   target  = (const int*)d_in[1];
    const float* conv1_w = (const float*)d_in[3];
    const float* conv1_b = (const float*)d_in[4];
    const float* ln1_g   = (const float*)d_in[5];
    const float* ln1_b   = (const float*)d_in[6];
    const float* conv2_w = (const float*)d_in[7];
    const float* conv2_b = (const float*)d_in[8];
    const float* ln2_g   = (const float*)d_in[9];
    const float* ln2_b   = (const float*)d_in[10];
    const float* lin_w   = (const float*)d_in[11];
    const float* lin_b   = (const float*)d_in[12];

    float* out_gather = (float*)d_out;
    float* out_dur    = (float*)d_out + OUT_GATHER_ELEMS;

    __nv_bfloat16 *w1p, *w2p, *xh, *xl, *h1h, *h1l;
    int* cum;
    cudaGetSymbolAddress((void**)&w1p, g_w1p);
    cudaGetSymbolAddress((void**)&w2p, g_w2p);
    cudaGetSymbolAddress((void**)&xh,  g_xh);
    cudaGetSymbolAddress((void**)&xl,  g_xl);
    cudaGetSymbolAddress((void**)&h1h, g_h1h);
    cudaGetSymbolAddress((void**)&h1l, g_h1l);
    cudaGetSymbolAddress((void**)&cum, g_cum);

    cudaFuncSetAttribute(conv_pipe_kernel<true>,
                         cudaFuncAttributeMaxDynamicSharedMemorySize, CONV_SMEM);
    cudaFuncSetAttribute(conv_pipe_kernel<false>,
                         cudaFuncAttributeMaxDynamicSharedMemorySize, CONV_SMEM);

    pack_all_kernel<<<2 * KTOT + MM * DD / 1024, 256>>>(
        conv1_w, conv2_w, x, w1p, w2p, xh, xl);
    cumsum_kernel<<<1, 1024>>>(target, cum);

    conv_pipe_kernel<true><<<MM / 128, 512, CONV_SMEM>>>(
        xh, xl, w1p,
        conv1_b, ln1_g, ln1_b, lin_w, lin_b, h1h, h1l, nullptr);

    conv_pipe_kernel<false><<<MM / 128, 512, CONV_SMEM>>>(
        h1h, h1l, w2p,
        conv2_b, ln2_g, ln2_b, lin_w, lin_b, nullptr, nullptr, out_dur);

    gather_kernel<<<dim3(MEL / 4, BB), 256>>>(x, cum, out_gather);
}

// round 14
// speedup vs baseline: 1.4509x; 1.0480x over previous
#include <cuda_runtime.h>
#include <cuda_bf16.h>
#include <cstdint>

#define BB 32
#define TT 512
#define DD 256
#define FF 256
#define MM (BB * TT)          // 16384
#define KTOT 768
#define MEL 2304
#define NCH 24                // K chunks of 32
#define OUT_GATHER_ELEMS (BB * MEL * DD)   // 18874368

// ---------------- device scratch (no allocs allowed) ----------------
// packed weights: per chunk 32KB = [hi 16KB][lo 16KB], each SW64-swizzled
__device__ __nv_bfloat16 g_w1p[NCH * 16384];
__device__ __nv_bfloat16 g_w2p[NCH * 16384];
__device__ __nv_bfloat16 g_xh[MM * DD];
__device__ __nv_bfloat16 g_xl[MM * DD];
__device__ __nv_bfloat16 g_h1h[MM * FF];
__device__ __nv_bfloat16 g_h1l[MM * FF];
__device__ int g_cum[BB * TT];

// ---------------- helpers ----------------
__device__ __forceinline__ uint32_t smem_u32(const void* p) {
    uint32_t a;
    asm("{ .reg .u64 t; cvta.to.shared.u64 t, %1; cvt.u32.u64 %0, t; }" : "=r"(a) : "l"(p));
    return a;
}
#define SW64(o) ((o) ^ (((o) >> 3) & 0x30))

__device__ __forceinline__ void ldmatrix_x4(uint32_t* r, uint32_t addr) {
    asm volatile("ldmatrix.sync.aligned.m8n8.x4.shared.b16 {%0,%1,%2,%3}, [%4];"
                 : "=r"(r[0]), "=r"(r[1]), "=r"(r[2]), "=r"(r[3]) : "r"(addr));
}

__device__ __forceinline__ void mma_bf16(float* c, const uint32_t* a, uint32_t b0, uint32_t b1) {
    asm volatile(
        "mma.sync.aligned.m16n8k16.row.col.f32.bf16.bf16.f32 "
        "{%0,%1,%2,%3}, {%4,%5,%6,%7}, {%8,%9}, {%0,%1,%2,%3};"
        : "+f"(c[0]), "+f"(c[1]), "+f"(c[2]), "+f"(c[3])
        : "r"(a[0]), "r"(a[1]), "r"(a[2]), "r"(a[3]), "r"(b0), "r"(b1));
}

__device__ __forceinline__ void cp16(uint32_t dst, const void* src, uint32_t srcsize) {
    asm volatile("cp.async.cg.shared.global [%0], [%1], 16, %2;"
                 :: "r"(dst), "l"(src), "r"(srcsize) : "memory");
}
#define CP_COMMIT()  asm volatile("cp.async.commit_group;" ::: "memory")
#define CP_WAITG(n)  asm volatile("cp.async.wait_group %0;" :: "n"(n) : "memory")

__device__ __forceinline__ void bulk_cp(uint32_t dst, const void* src, uint32_t bytes,
                                        uint32_t mbar) {
    asm volatile(
        "cp.async.bulk.shared::cta.global.mbarrier::complete_tx::bytes [%0], [%1], %2, [%3];"
        :: "r"(dst), "l"(src), "r"(bytes), "r"(mbar) : "memory");
}
#define MBAR_INIT(mb, n) \
    asm volatile("mbarrier.init.shared.b64 [%0], %1;" :: "r"(mb), "r"(n) : "memory")
#define MBAR_EXPECT(mb, tx) \
    asm volatile("mbarrier.arrive.expect_tx.shared.b64 _, [%0], %1;" :: "r"(mb), "r"(tx) : "memory")
#define MBAR_WAIT(mb, par) do {                                               \
    uint32_t _mb = (mb); uint32_t _p = (par); uint32_t _done;                 \
    asm volatile("{\n\t.reg .pred p;\n\t"                                     \
        "mbarrier.try_wait.parity.acquire.cta.shared::cta.b64 p, [%1], %2;\n\t" \
        "selp.b32 %0, 1, 0, p;\n\t}"                                          \
        : "=r"(_done) : "r"(_mb), "r"(_p) : "memory");                        \
    if (!_done) {                                                             \
        asm volatile("{\n\t.reg .pred P1;\n\t"                                \
            "WL_%=:\n\t"                                                      \
            "mbarrier.try_wait.parity.acquire.cta.shared::cta.b64 P1, [%0], %1, 0x989680;\n\t" \
            "@P1 bra.uni WD_%=;\n\tbra.uni WL_%=;\n\tWD_%=:\n\t}"             \
            :: "r"(_mb), "r"(_p) : "memory");                                 \
    }                                                                         \
} while (0)

__device__ __forceinline__ void split_bf16(float v, __nv_bfloat16& hi, __nv_bfloat16& lo) {
    hi = __float2bfloat16_rn(v);
    lo = __float2bfloat16_rn(v - __bfloat162float(hi));
}

// ---------------- SMEM layout (dynamic) ----------------
#define A_HI 0
#define A_LO 10240
#define B_BLK 20480
#define STAGE_STRIDE 53248
#define P_CB   212992
#define P_LG   214016
#define P_LB   215040
#define P_LW   216064
#define S_SUM  217088
#define S_SQ   219136
#define S_DOT  221184
#define SM_MBAR 223232
#define CONV_SMEM 223296

// ---------------- merged pack: w1, w2 (SW64 chunk blocks) + x split ---------
__global__ void pack_all_kernel(const float* __restrict__ w1, const float* __restrict__ w2,
                                const float* __restrict__ x,
                                __nv_bfloat16* __restrict__ w1p, __nv_bfloat16* __restrict__ w2p,
                                __nv_bfloat16* __restrict__ xh, __nv_bfloat16* __restrict__ xl) {
    int bid = blockIdx.x;
    if (bid < 2 * KTOT) {
        const float* w = (bid < KTOT) ? w1 : w2;
        __nv_bfloat16* wp = (bid < KTOT) ? w1p : w2p;
        int o = (bid % KTOT) * 256 + threadIdx.x;
        int f = o / KTOT;
        int rem = o - f * KTOT;
        int tap = rem >> 8;
        int d = rem & 255;
        int kk = tap * 256 + d;
        float v = w[(f * DD + d) * 3 + tap];
        __nv_bfloat16 hi, lo;
        split_bf16(v, hi, lo);
        int ch = kk >> 5;
        int inner = kk & 31;
        uint32_t sw = SW64((uint32_t)(f * 64 + inner * 2));
        wp[ch * 16384 + (sw >> 1)] = hi;
        wp[ch * 16384 + 8192 + (sw >> 1)] = lo;
    } else {
        int o = ((bid - 2 * KTOT) * 256 + threadIdx.x) * 4;
        float4 v = *(const float4*)(x + o);
        __nv_bfloat16 h[4], l[4];
        split_bf16(v.x, h[0], l[0]); split_bf16(v.y, h[1], l[1]);
        split_bf16(v.z, h[2], l[2]); split_bf16(v.w, h[3], l[3]);
        *(uint2*)(xh + o) = *(uint2*)h;
        *(uint2*)(xl + o) = *(uint2*)l;
    }
}

// ---------------- conv+bias+LN+ReLU: BM=128 x BN=256, BK=32 -----------------
// 512 threads, 4-stage pipeline, A via cp16, B via bulk copy (SW64 pre-swizzle).
// Inner loop: ALL LDSM hoisted, MMAs term-major (reuse distance 16).
template <bool OUT_SPLIT>
__global__ void __launch_bounds__(512, 1)
conv_pipe_kernel(const __nv_bfloat16* __restrict__ inh,
                 const __nv_bfloat16* __restrict__ inl,
                 const __nv_bfloat16* __restrict__ wp,
                 const float* __restrict__ cb, const float* __restrict__ lg,
                 const float* __restrict__ lb, const float* __restrict__ lw,
                 const float* __restrict__ lbias,
                 __nv_bfloat16* __restrict__ outh, __nv_bfloat16* __restrict__ outl,
                 float* __restrict__ dur) {
    extern __shared__ char smem[];
    const uint32_t sb = smem_u32(smem);
    const int tid = threadIdx.x;
    const int warp = tid >> 5, lane = tid & 31;
    const int wm = warp & 3, wn = warp >> 2;
    const int m0 = blockIdx.x * 128;

    if (tid < 256) {
        ((float*)(smem + P_CB))[tid] = cb[tid];
        ((float*)(smem + P_LG))[tid] = lg[tid];
        ((float*)(smem + P_LB))[tid] = lb[tid];
        ((float*)(smem + P_LW))[tid] = lw[tid];
    }
    if (tid == 0) {
#pragma unroll
        for (int i = 0; i < 4; ++i) MBAR_INIT(sb + SM_MBAR + i * 8, 1);
    }
    __syncthreads();

    float acc[2][8][4];
#pragma unroll
    for (int mi = 0; mi < 2; ++mi)
#pragma unroll
        for (int j = 0; j < 8; ++j)
#pragma unroll
            for (int e = 0; e < 4; ++e) acc[mi][j][e] = 0.f;

    const int lrow = tid >> 2;
    const int lq   = tid & 3;
    const int am = m0 + lrow;
    const int at = am & (TT - 1);

    auto load_stage = [&](int ch) {
        const uint32_t base = sb + (uint32_t)((ch & 3) * STAGE_STRIDE);
        const int kk0 = ch * 32;
        const int tap = kk0 >> 8;
        const int d0  = kk0 & 255;
        const int dt  = tap - 1;
        {
            int tt = at + dt;
            uint32_t ok = (tt >= 0 && tt < TT) ? 16u : 0u;
            int ttc = min(max(tt, 0), TT - 1);
            size_t goff = (size_t)(am - at + ttc) * DD + d0 + lq * 8;
            uint32_t soff = (uint32_t)(lrow * 80 + lq * 16);
            cp16(base + A_HI + soff, inh + goff, ok);
            cp16(base + A_LO + soff, inl + goff, ok);
        }
        CP_COMMIT();
        if (tid == 0) {
            uint32_t mb = sb + SM_MBAR + (ch & 3) * 8;
            MBAR_EXPECT(mb, 32768u);
            bulk_cp(base + B_BLK, (const char*)wp + (size_t)ch * 32768, 32768u, mb);
        }
    };

    uint32_t a_off[2];
#pragma unroll
    for (int mi = 0; mi < 2; ++mi)
        a_off[mi] = (uint32_t)((wm * 32 + mi * 16 + (lane & 15)) * 80 + ((lane >> 4) & 1) * 16);
    uint32_t b_base[4];
#pragma unroll
    for (int jp = 0; jp < 4; ++jp) {
        int row = wn * 64 + jp * 16 + (lane & 7) + ((lane >> 4) & 1) * 8;
        b_base[jp] = (uint32_t)(row * 64 + ((lane >> 3) & 1) * 16);
    }

    load_stage(0);
    load_stage(1);
    load_stage(2);

    for (int ch = 0; ch < NCH; ++ch) {
        if (ch <= NCH - 3)      { CP_WAITG(2); }
        else if (ch == NCH - 2) { CP_WAITG(1); }
        else                    { CP_WAITG(0); }
        MBAR_WAIT(sb + SM_MBAR + (ch & 3) * 8, (ch >> 2) & 1);
        __syncthreads();
        if (ch + 3 < NCH) load_stage(ch + 3);

        const uint32_t base = sb + (uint32_t)((ch & 3) * STAGE_STRIDE);
        const uint32_t bblk = base + B_BLK;
#pragma unroll
        for (int s = 0; s < 2; ++s) {
            // hoist ALL fragment loads for this k-step
            uint32_t ah[2][4], al[2][4], bh[4][4], bl[4][4];
#pragma unroll
            for (int mi = 0; mi < 2; ++mi) {
                ldmatrix_x4(ah[mi], base + A_HI + a_off[mi] + s * 32);
                ldmatrix_x4(al[mi], base + A_LO + a_off[mi] + s * 32);
            }
#pragma unroll
            for (int jp = 0; jp < 4; ++jp) {
                uint32_t sw = SW64(b_base[jp] + s * 32);
                ldmatrix_x4(bh[jp], bblk + sw);
                ldmatrix_x4(bl[jp], bblk + 16384 + sw);
            }
            // term hh: ah * bh
#pragma unroll
            for (int jp = 0; jp < 4; ++jp)
#pragma unroll
                for (int mi = 0; mi < 2; ++mi) {
                    mma_bf16(acc[mi][jp * 2],     ah[mi], bh[jp][0], bh[jp][1]);
                    mma_bf16(acc[mi][jp * 2 + 1], ah[mi], bh[jp][2], bh[jp][3]);
                }
            // term hl: ah * bl
#pragma unroll
            for (int jp = 0; jp < 4; ++jp)
#pragma unroll
                for (int mi = 0; mi < 2; ++mi) {
                    mma_bf16(acc[mi][jp * 2],     ah[mi], bl[jp][0], bl[jp][1]);
                    mma_bf16(acc[mi][jp * 2 + 1], ah[mi], bl[jp][2], bl[jp][3]);
                }
            // term lh: al * bh
#pragma unroll
            for (int jp = 0; jp < 4; ++jp)
#pragma unroll
                for (int mi = 0; mi < 2; ++mi) {
                    mma_bf16(acc[mi][jp * 2],     al[mi], bh[jp][0], bh[jp][1]);
                    mma_bf16(acc[mi][jp * 2 + 1], al[mi], bh[jp][2], bh[jp][3]);
                }
        }
    }
    __syncthreads();

    // ---------------- epilogue: +bias, LayerNorm(256), ReLU -----------------
    const float* scb = (const float*)(smem + P_CB);
    const float* slg = (const float*)(smem + P_LG);
    const float* slb = (const float*)(smem + P_LB);
    const float* slw = (const float*)(smem + P_LW);
    float* ssum = (float*)(smem + S_SUM);
    float* ssq  = (float*)(smem + S_SQ);
    float* sdot = (float*)(smem + S_DOT);

    float ps[2][2], pq[2][2];
#pragma unroll
    for (int mi = 0; mi < 2; ++mi)
#pragma unroll
        for (int h = 0; h < 2; ++h) { ps[mi][h] = 0.f; pq[mi][h] = 0.f; }

#pragma unroll
    for (int mi = 0; mi < 2; ++mi)
#pragma unroll
        for (int j = 0; j < 8; ++j) {
            int cj = wn * 64 + (j >> 1) * 16 + (j & 1) * 8 + (lane & 3) * 2;
            float b0v = scb[cj], b1v = scb[cj + 1];
            float v0 = acc[mi][j][0] + b0v, v1 = acc[mi][j][1] + b1v;
            float v2 = acc[mi][j][2] + b0v, v3 = acc[mi][j][3] + b1v;
            acc[mi][j][0] = v0; acc[mi][j][1] = v1;
            acc[mi][j][2] = v2; acc[mi][j][3] = v3;
            ps[mi][0] += v0 + v1; pq[mi][0] += v0 * v0 + v1 * v1;
            ps[mi][1] += v2 + v3; pq[mi][1] += v2 * v2 + v3 * v3;
        }
#pragma unroll
    for (int off = 1; off <= 2; off <<= 1)
#pragma unroll
        for (int mi = 0; mi < 2; ++mi)
#pragma unroll
            for (int h = 0; h < 2; ++h) {
                ps[mi][h] += __shfl_xor_sync(0xffffffffu, ps[mi][h], off);
                pq[mi][h] += __shfl_xor_sync(0xffffffffu, pq[mi][h], off);
            }
    const int rbase = wm * 32 + (lane >> 2);
    if ((lane & 3) == 0) {
#pragma unroll
        for (int mi = 0; mi < 2; ++mi)
#pragma unroll
            for (int h = 0; h < 2; ++h) {
                int r = rbase + mi * 16 + h * 8;
                ssum[wn * 128 + r] = ps[mi][h];
                ssq[wn * 128 + r]  = pq[mi][h];
            }
    }
    __syncthreads();

    float dot[2][2] = {{0.f, 0.f}, {0.f, 0.f}};
#pragma unroll
    for (int mi = 0; mi < 2; ++mi)
#pragma unroll
        for (int h = 0; h < 2; ++h) {
            int r = rbase + mi * 16 + h * 8;
            float S = ssum[r] + ssum[128 + r] + ssum[256 + r] + ssum[384 + r];
            float Q = ssq[r]  + ssq[128 + r]  + ssq[256 + r]  + ssq[384 + r];
            float mu = S * (1.f / 256.f);
            float rs = rsqrtf(Q * (1.f / 256.f) - mu * mu + 1e-5f);
#pragma unroll
            for (int j = 0; j < 8; ++j) {
                int cj = wn * 64 + (j >> 1) * 16 + (j & 1) * 8 + (lane & 3) * 2;
                float g0 = slg[cj], g1 = slg[cj + 1];
                float d0v = slb[cj], d1v = slb[cj + 1];
                float v0 = fmaxf(fmaf((acc[mi][j][h * 2]     - mu) * rs, g0, d0v), 0.f);
                float v1 = fmaxf(fmaf((acc[mi][j][h * 2 + 1] - mu) * rs, g1, d1v), 0.f);
                if (OUT_SPLIT) {
                    __nv_bfloat16 h0, l0, h1, l1;
                    split_bf16(v0, h0, l0); split_bf16(v1, h1, l1);
                    size_t idx = (size_t)(m0 + r) * FF + cj;
                    *(__nv_bfloat162*)(outh + idx) = __nv_bfloat162(h0, h1);
                    *(__nv_bfloat162*)(outl + idx) = __nv_bfloat162(l0, l1);
                } else {
                    dot[mi][h] = fmaf(v0, slw[cj], fmaf(v1, slw[cj + 1], dot[mi][h]));
                }
            }
        }
    if (!OUT_SPLIT) {
#pragma unroll
        for (int off = 1; off <= 2; off <<= 1)
#pragma unroll
            for (int mi = 0; mi < 2; ++mi)
#pragma unroll
                for (int h = 0; h < 2; ++h)
                    dot[mi][h] += __shfl_xor_sync(0xffffffffu, dot[mi][h], off);
        if ((lane & 3) == 0) {
#pragma unroll
            for (int mi = 0; mi < 2; ++mi)
#pragma unroll
                for (int h = 0; h < 2; ++h) {
                    int r = rbase + mi * 16 + h * 8;
                    sdot[wn * 128 + r] = dot[mi][h];
                }
        }
        __syncthreads();
        if (tid < 128)
            dur[m0 + tid] = fmaxf(sdot[tid] + sdot[128 + tid] + sdot[256 + tid] +
                                  sdot[384 + tid] + lbias[0], 0.f);
    }
}

// ---------------- cumsum: one block, warp per batch --------------------------
__global__ void cumsum_kernel(const int* __restrict__ target, int* __restrict__ cum) {
    int w = threadIdx.x >> 5;
    int l = threadIdx.x & 31;
    const int* src = target + w * TT;
    int* dst = cum + w * TT;
    int v[16];
    int s = 0;
#pragma unroll
    for (int i = 0; i < 16; ++i) { v[i] = src[l * 16 + i]; s += v[i]; }
    int p = s;
#pragma unroll
    for (int off = 1; off < 32; off <<= 1) {
        int u = __shfl_up_sync(0xffffffffu, p, off);
        if (l >= off) p += u;
    }
    int run = p - s;
#pragma unroll
    for (int i = 0; i < 16; ++i) { run += v[i]; dst[l * 16 + i] = run; }
}

// ---------------- length-regulator gather: 64 rows/block ---------------------
__global__ void __launch_bounds__(512, 2)
gather_kernel(const float* __restrict__ x, const int* __restrict__ cum,
              float* __restrict__ out) {
    __shared__ int sc[TT];
    int b = blockIdx.y;
    sc[threadIdx.x] = cum[b * TT + threadIdx.x];
    __syncthreads();
    int total = sc[TT - 1];
    int t_out = blockIdx.x * 64 + (threadIdx.x >> 3);   // 64 rows, 8 threads/row
    int sub   = threadIdx.x & 7;
    int lo = 0, hi = TT;
    while (lo < hi) {
        int mid = (lo + hi) >> 1;
        if (sc[mid] <= t_out) lo = mid + 1; else hi = mid;
    }
    int idx = min(lo, TT - 1);
    bool valid = t_out < total;
    const float4* src = (const float4*)(x + ((size_t)(b * TT + idx)) * DD);
    float4* dst = (float4*)(out + ((size_t)(b * MEL + t_out)) * DD);
    float4 z = make_float4(0.f, 0.f, 0.f, 0.f);
#pragma unroll
    for (int i = 0; i < 8; ++i)
        dst[sub + i * 8] = valid ? src[sub + i * 8] : z;
}

// ---------------- launch ----------------------------------------------------
extern "C" void kernel_launch(void* const* d_in, const int* in_sizes, int n_in,
                              void* d_out, int out_size) {
    const float* x       = (const float*)d_in[0];
    const int*   target  = (const int*)d_in[1];
    const float* conv1_w = (const float*)d_in[3];
    const float* conv1_b = (const float*)d_in[4];
    const float* ln1_g   = (const float*)d_in[5];
    const float* ln1_b   = (const float*)d_in[6];
    const float* conv2_w = (const float*)d_in[7];
    const float* conv2_b = (const float*)d_in[8];
    const float* ln2_g   = (const float*)d_in[9];
    const float* ln2_b   = (const float*)d_in[10];
    const float* lin_w   = (const float*)d_in[11];
    const float* lin_b   = (const float*)d_in[12];

    float* out_gather = (float*)d_out;
    float* out_dur    = (float*)d_out + OUT_GATHER_ELEMS;

    __nv_bfloat16 *w1p, *w2p, *xh, *xl, *h1h, *h1l;
    int* cum;
    cudaGetSymbolAddress((void**)&w1p, g_w1p);
    cudaGetSymbolAddress((void**)&w2p, g_w2p);
    cudaGetSymbolAddress((void**)&xh,  g_xh);
    cudaGetSymbolAddress((void**)&xl,  g_xl);
    cudaGetSymbolAddress((void**)&h1h, g_h1h);
    cudaGetSymbolAddress((void**)&h1l, g_h1l);
    cudaGetSymbolAddress((void**)&cum, g_cum);

    cudaFuncSetAttribute(conv_pipe_kernel<true>,
                         cudaFuncAttributeMaxDynamicSharedMemorySize, CONV_SMEM);
    cudaFuncSetAttribute(conv_pipe_kernel<false>,
                         cudaFuncAttributeMaxDynamicSharedMemorySize, CONV_SMEM);

    pack_all_kernel<<<2 * KTOT + MM * DD / 1024, 256>>>(
        conv1_w, conv2_w, x, w1p, w2p, xh, xl);
    cumsum_kernel<<<1, 1024>>>(target, cum);

    conv_pipe_kernel<true><<<MM / 128, 512, CONV_SMEM>>>(
        xh, xl, w1p,
        conv1_b, ln1_g, ln1_b, lin_w, lin_b, h1h, h1l, nullptr);

    conv_pipe_kernel<false><<<MM / 128, 512, CONV_SMEM>>>(
        h1h, h1l, w2p,
        conv2_b, ln2_g, ln2_b, lin_w, lin_b, nullptr, nullptr, out_dur);

    gather_kernel<<<dim3(MEL / 64, BB), 512>>>(x, cum, out_gather);
}

// round 15
// speedup vs baseline: 1.5163x; 1.0451x over previous
#include <cuda_runtime.h>
#include <cuda_bf16.h>
#include <cstdint>

#define BB 32
#define TT 512
#define DD 256
#define FF 256
#define MM (BB * TT)          // 16384
#define KTOT 768
#define MEL 2304
#define NCH 24                // K chunks of 32
#define OUT_GATHER_ELEMS (BB * MEL * DD)   // 18874368

// ---------------- device scratch (no allocs allowed) ----------------
// packed weights: per chunk 32KB = [hi 16KB][lo 16KB], each SW64-swizzled
__device__ __nv_bfloat16 g_w1p[NCH * 16384];
__device__ __nv_bfloat16 g_w2p[NCH * 16384];
__device__ __nv_bfloat16 g_xh[MM * DD];
__device__ __nv_bfloat16 g_xl[MM * DD];
__device__ __nv_bfloat16 g_h1h[MM * FF];
__device__ __nv_bfloat16 g_h1l[MM * FF];
__device__ int g_cum[BB * TT];

// ---------------- helpers ----------------
__device__ __forceinline__ uint32_t smem_u32(const void* p) {
    uint32_t a;
    asm("{ .reg .u64 t; cvta.to.shared.u64 t, %1; cvt.u32.u64 %0, t; }" : "=r"(a) : "l"(p));
    return a;
}
#define SW64(o) ((o) ^ (((o) >> 3) & 0x30))

__device__ __forceinline__ void ldmatrix_x4(uint32_t* r, uint32_t addr) {
    asm volatile("ldmatrix.sync.aligned.m8n8.x4.shared.b16 {%0,%1,%2,%3}, [%4];"
                 : "=r"(r[0]), "=r"(r[1]), "=r"(r[2]), "=r"(r[3]) : "r"(addr));
}

__device__ __forceinline__ void mma_bf16(float* c, const uint32_t* a, uint32_t b0, uint32_t b1) {
    asm volatile(
        "mma.sync.aligned.m16n8k16.row.col.f32.bf16.bf16.f32 "
        "{%0,%1,%2,%3}, {%4,%5,%6,%7}, {%8,%9}, {%0,%1,%2,%3};"
        : "+f"(c[0]), "+f"(c[1]), "+f"(c[2]), "+f"(c[3])
        : "r"(a[0]), "r"(a[1]), "r"(a[2]), "r"(a[3]), "r"(b0), "r"(b1));
}

__device__ __forceinline__ void cp16(uint32_t dst, const void* src, uint32_t srcsize) {
    asm volatile("cp.async.cg.shared.global [%0], [%1], 16, %2;"
                 :: "r"(dst), "l"(src), "r"(srcsize) : "memory");
}
#define CP_COMMIT()  asm volatile("cp.async.commit_group;" ::: "memory")
#define CP_WAITG(n)  asm volatile("cp.async.wait_group %0;" :: "n"(n) : "memory")

__device__ __forceinline__ void bulk_cp(uint32_t dst, const void* src, uint32_t bytes,
                                        uint32_t mbar) {
    asm volatile(
        "cp.async.bulk.shared::cta.global.mbarrier::complete_tx::bytes [%0], [%1], %2, [%3];"
        :: "r"(dst), "l"(src), "r"(bytes), "r"(mbar) : "memory");
}
#define MBAR_INIT(mb, n) \
    asm volatile("mbarrier.init.shared.b64 [%0], %1;" :: "r"(mb), "r"(n) : "memory")
#define MBAR_EXPECT(mb, tx) \
    asm volatile("mbarrier.arrive.expect_tx.shared.b64 _, [%0], %1;" :: "r"(mb), "r"(tx) : "memory")
#define MBAR_WAIT(mb, par) do {                                               \
    uint32_t _mb = (mb); uint32_t _p = (par); uint32_t _done;                 \
    asm volatile("{\n\t.reg .pred p;\n\t"                                     \
        "mbarrier.try_wait.parity.acquire.cta.shared::cta.b64 p, [%1], %2;\n\t" \
        "selp.b32 %0, 1, 0, p;\n\t}"                                          \
        : "=r"(_done) : "r"(_mb), "r"(_p) : "memory");                        \
    if (!_done) {                                                             \
        asm volatile("{\n\t.reg .pred P1;\n\t"                                \
            "WL_%=:\n\t"                                                      \
            "mbarrier.try_wait.parity.acquire.cta.shared::cta.b64 P1, [%0], %1, 0x989680;\n\t" \
            "@P1 bra.uni WD_%=;\n\tbra.uni WL_%=;\n\tWD_%=:\n\t}"             \
            :: "r"(_mb), "r"(_p) : "memory");                                 \
    }                                                                         \
} while (0)

__device__ __forceinline__ void split_bf16(float v, __nv_bfloat16& hi, __nv_bfloat16& lo) {
    hi = __float2bfloat16_rn(v);
    lo = __float2bfloat16_rn(v - __bfloat162float(hi));
}

// ---------------- SMEM layout (dynamic) ----------------
#define A_HI 0
#define A_LO 10240
#define B_BLK 20480
#define STAGE_STRIDE 53248
#define P_CB   212992
#define P_LG   214016
#define P_LB   215040
#define P_LW   216064
#define S_SUM  217088
#define S_SQ   219136
#define S_DOT  221184
#define SM_MBAR 223232
#define CONV_SMEM 223296

// ---------------- merged pack: w1, w2 (SW64 chunk blocks) + x split ---------
__global__ void pack_all_kernel(const float* __restrict__ w1, const float* __restrict__ w2,
                                const float* __restrict__ x,
                                __nv_bfloat16* __restrict__ w1p, __nv_bfloat16* __restrict__ w2p,
                                __nv_bfloat16* __restrict__ xh, __nv_bfloat16* __restrict__ xl) {
    int bid = blockIdx.x;
    if (bid < 2 * KTOT) {
        const float* w = (bid < KTOT) ? w1 : w2;
        __nv_bfloat16* wp = (bid < KTOT) ? w1p : w2p;
        int o = (bid % KTOT) * 256 + threadIdx.x;
        int f = o / KTOT;
        int rem = o - f * KTOT;
        int tap = rem >> 8;
        int d = rem & 255;
        int kk = tap * 256 + d;
        float v = w[(f * DD + d) * 3 + tap];
        __nv_bfloat16 hi, lo;
        split_bf16(v, hi, lo);
        int ch = kk >> 5;
        int inner = kk & 31;
        uint32_t sw = SW64((uint32_t)(f * 64 + inner * 2));
        wp[ch * 16384 + (sw >> 1)] = hi;
        wp[ch * 16384 + 8192 + (sw >> 1)] = lo;
    } else {
        int o = ((bid - 2 * KTOT) * 256 + threadIdx.x) * 4;
        float4 v = *(const float4*)(x + o);
        __nv_bfloat16 h[4], l[4];
        split_bf16(v.x, h[0], l[0]); split_bf16(v.y, h[1], l[1]);
        split_bf16(v.z, h[2], l[2]); split_bf16(v.w, h[3], l[3]);
        *(uint2*)(xh + o) = *(uint2*)h;
        *(uint2*)(xl + o) = *(uint2*)l;
    }
}

// ---------------- conv+bias+LN+ReLU: BM=128 x BN=256, BK=32 -----------------
// 512 threads (4m x 4n warps, warp tile 32x64), 4-stage pipeline:
// A via cp.async (cp16), B via ONE cp.async.bulk per stage (pre-swizzled SW64),
// one __syncthreads per chunk, R11 interleaved inner loop (proven fastest).
template <bool OUT_SPLIT>
__global__ void __launch_bounds__(512, 1)
conv_pipe_kernel(const __nv_bfloat16* __restrict__ inh,
                 const __nv_bfloat16* __restrict__ inl,
                 const __nv_bfloat16* __restrict__ wp,
                 const float* __restrict__ cb, const float* __restrict__ lg,
                 const float* __restrict__ lb, const float* __restrict__ lw,
                 const float* __restrict__ lbias,
                 __nv_bfloat16* __restrict__ outh, __nv_bfloat16* __restrict__ outl,
                 float* __restrict__ dur) {
    extern __shared__ char smem[];
    const uint32_t sb = smem_u32(smem);
    const int tid = threadIdx.x;
    const int warp = tid >> 5, lane = tid & 31;
    const int wm = warp & 3, wn = warp >> 2;
    const int m0 = blockIdx.x * 128;

    if (tid < 256) {
        ((float*)(smem + P_CB))[tid] = cb[tid];
        ((float*)(smem + P_LG))[tid] = lg[tid];
        ((float*)(smem + P_LB))[tid] = lb[tid];
        ((float*)(smem + P_LW))[tid] = lw[tid];
    }
    if (tid == 0) {
#pragma unroll
        for (int i = 0; i < 4; ++i) MBAR_INIT(sb + SM_MBAR + i * 8, 1);
    }
    __syncthreads();

    float acc[2][8][4];
#pragma unroll
    for (int mi = 0; mi < 2; ++mi)
#pragma unroll
        for (int j = 0; j < 8; ++j)
#pragma unroll
            for (int e = 0; e < 4; ++e) acc[mi][j][e] = 0.f;

    const int lrow = tid >> 2;
    const int lq   = tid & 3;
    const int am = m0 + lrow;
    const int at = am & (TT - 1);

    auto load_stage = [&](int ch) {
        const uint32_t base = sb + (uint32_t)((ch & 3) * STAGE_STRIDE);
        const int kk0 = ch * 32;
        const int tap = kk0 >> 8;
        const int d0  = kk0 & 255;
        const int dt  = tap - 1;
        {
            int tt = at + dt;
            uint32_t ok = (tt >= 0 && tt < TT) ? 16u : 0u;
            int ttc = min(max(tt, 0), TT - 1);
            size_t goff = (size_t)(am - at + ttc) * DD + d0 + lq * 8;
            uint32_t soff = (uint32_t)(lrow * 80 + lq * 16);
            cp16(base + A_HI + soff, inh + goff, ok);
            cp16(base + A_LO + soff, inl + goff, ok);
        }
        CP_COMMIT();
        if (tid == 0) {
            uint32_t mb = sb + SM_MBAR + (ch & 3) * 8;
            MBAR_EXPECT(mb, 32768u);
            bulk_cp(base + B_BLK, (const char*)wp + (size_t)ch * 32768, 32768u, mb);
        }
    };

    uint32_t a_off[2];
#pragma unroll
    for (int mi = 0; mi < 2; ++mi)
        a_off[mi] = (uint32_t)((wm * 32 + mi * 16 + (lane & 15)) * 80 + ((lane >> 4) & 1) * 16);
    uint32_t b_base[4];
#pragma unroll
    for (int jp = 0; jp < 4; ++jp) {
        int row = wn * 64 + jp * 16 + (lane & 7) + ((lane >> 4) & 1) * 8;
        b_base[jp] = (uint32_t)(row * 64 + ((lane >> 3) & 1) * 16);
    }

    load_stage(0);
    load_stage(1);
    load_stage(2);

    for (int ch = 0; ch < NCH; ++ch) {
        if (ch <= NCH - 3)      { CP_WAITG(2); }
        else if (ch == NCH - 2) { CP_WAITG(1); }
        else                    { CP_WAITG(0); }
        MBAR_WAIT(sb + SM_MBAR + (ch & 3) * 8, (ch >> 2) & 1);
        __syncthreads();
        if (ch + 3 < NCH) load_stage(ch + 3);

        const uint32_t base = sb + (uint32_t)((ch & 3) * STAGE_STRIDE);
        const uint32_t bblk = base + B_BLK;
#pragma unroll
        for (int s = 0; s < 2; ++s) {
            uint32_t ah[2][4], al[2][4];
#pragma unroll
            for (int mi = 0; mi < 2; ++mi) {
                ldmatrix_x4(ah[mi], base + A_HI + a_off[mi] + s * 32);
                ldmatrix_x4(al[mi], base + A_LO + a_off[mi] + s * 32);
            }
#pragma unroll
            for (int jp = 0; jp < 4; ++jp) {
                uint32_t sw = SW64(b_base[jp] + s * 32);
                uint32_t bh[4], bl[4];
                ldmatrix_x4(bh, bblk + sw);
                ldmatrix_x4(bl, bblk + 16384 + sw);
#pragma unroll
                for (int mi = 0; mi < 2; ++mi) {
                    mma_bf16(acc[mi][jp * 2],     ah[mi], bh[0], bh[1]);
                    mma_bf16(acc[mi][jp * 2 + 1], ah[mi], bh[2], bh[3]);
                    mma_bf16(acc[mi][jp * 2],     ah[mi], bl[0], bl[1]);
                    mma_bf16(acc[mi][jp * 2 + 1], ah[mi], bl[2], bl[3]);
                    mma_bf16(acc[mi][jp * 2],     al[mi], bh[0], bh[1]);
                    mma_bf16(acc[mi][jp * 2 + 1], al[mi], bh[2], bh[3]);
                }
            }
        }
    }
    __syncthreads();

    // ---------------- epilogue: +bias, LayerNorm(256), ReLU -----------------
    const float* scb = (const float*)(smem + P_CB);
    const float* slg = (const float*)(smem + P_LG);
    const float* slb = (const float*)(smem + P_LB);
    const float* slw = (const float*)(smem + P_LW);
    float* ssum = (float*)(smem + S_SUM);
    float* ssq  = (float*)(smem + S_SQ);
    float* sdot = (float*)(smem + S_DOT);

    float ps[2][2], pq[2][2];
#pragma unroll
    for (int mi = 0; mi < 2; ++mi)
#pragma unroll
        for (int h = 0; h < 2; ++h) { ps[mi][h] = 0.f; pq[mi][h] = 0.f; }

#pragma unroll
    for (int mi = 0; mi < 2; ++mi)
#pragma unroll
        for (int j = 0; j < 8; ++j) {
            int cj = wn * 64 + (j >> 1) * 16 + (j & 1) * 8 + (lane & 3) * 2;
            float b0v = scb[cj], b1v = scb[cj + 1];
            float v0 = acc[mi][j][0] + b0v, v1 = acc[mi][j][1] + b1v;
            float v2 = acc[mi][j][2] + b0v, v3 = acc[mi][j][3] + b1v;
            acc[mi][j][0] = v0; acc[mi][j][1] = v1;
            acc[mi][j][2] = v2; acc[mi][j][3] = v3;
            ps[mi][0] += v0 + v1; pq[mi][0] += v0 * v0 + v1 * v1;
            ps[mi][1] += v2 + v3; pq[mi][1] += v2 * v2 + v3 * v3;
        }
#pragma unroll
    for (int off = 1; off <= 2; off <<= 1)
#pragma unroll
        for (int mi = 0; mi < 2; ++mi)
#pragma unroll
            for (int h = 0; h < 2; ++h) {
                ps[mi][h] += __shfl_xor_sync(0xffffffffu, ps[mi][h], off);
                pq[mi][h] += __shfl_xor_sync(0xffffffffu, pq[mi][h], off);
            }
    const int rbase = wm * 32 + (lane >> 2);
    if ((lane & 3) == 0) {
#pragma unroll
        for (int mi = 0; mi < 2; ++mi)
#pragma unroll
            for (int h = 0; h < 2; ++h) {
                int r = rbase + mi * 16 + h * 8;
                ssum[wn * 128 + r] = ps[mi][h];
                ssq[wn * 128 + r]  = pq[mi][h];
            }
    }
    __syncthreads();

    float dot[2][2] = {{0.f, 0.f}, {0.f, 0.f}};
#pragma unroll
    for (int mi = 0; mi < 2; ++mi)
#pragma unroll
        for (int h = 0; h < 2; ++h) {
            int r = rbase + mi * 16 + h * 8;
            float S = ssum[r] + ssum[128 + r] + ssum[256 + r] + ssum[384 + r];
            float Q = ssq[r]  + ssq[128 + r]  + ssq[256 + r]  + ssq[384 + r];
            float mu = S * (1.f / 256.f);
            float rs = rsqrtf(Q * (1.f / 256.f) - mu * mu + 1e-5f);
#pragma unroll
            for (int j = 0; j < 8; ++j) {
                int cj = wn * 64 + (j >> 1) * 16 + (j & 1) * 8 + (lane & 3) * 2;
                float g0 = slg[cj], g1 = slg[cj + 1];
                float d0v = slb[cj], d1v = slb[cj + 1];
                float v0 = fmaxf(fmaf((acc[mi][j][h * 2]     - mu) * rs, g0, d0v), 0.f);
                float v1 = fmaxf(fmaf((acc[mi][j][h * 2 + 1] - mu) * rs, g1, d1v), 0.f);
                if (OUT_SPLIT) {
                    __nv_bfloat16 h0, l0, h1, l1;
                    split_bf16(v0, h0, l0); split_bf16(v1, h1, l1);
                    size_t idx = (size_t)(m0 + r) * FF + cj;
                    *(__nv_bfloat162*)(outh + idx) = __nv_bfloat162(h0, h1);
                    *(__nv_bfloat162*)(outl + idx) = __nv_bfloat162(l0, l1);
                } else {
                    dot[mi][h] = fmaf(v0, slw[cj], fmaf(v1, slw[cj + 1], dot[mi][h]));
                }
            }
        }
    if (!OUT_SPLIT) {
#pragma unroll
        for (int off = 1; off <= 2; off <<= 1)
#pragma unroll
            for (int mi = 0; mi < 2; ++mi)
#pragma unroll
                for (int h = 0; h < 2; ++h)
                    dot[mi][h] += __shfl_xor_sync(0xffffffffu, dot[mi][h], off);
        if ((lane & 3) == 0) {
#pragma unroll
            for (int mi = 0; mi < 2; ++mi)
#pragma unroll
                for (int h = 0; h < 2; ++h) {
                    int r = rbase + mi * 16 + h * 8;
                    sdot[wn * 128 + r] = dot[mi][h];
                }
        }
        __syncthreads();
        if (tid < 128)
            dur[m0 + tid] = fmaxf(sdot[tid] + sdot[128 + tid] + sdot[256 + tid] +
                                  sdot[384 + tid] + lbias[0], 0.f);
    }
}

// ---------------- cumsum: one block, warp per batch --------------------------
__global__ void cumsum_kernel(const int* __restrict__ target, int* __restrict__ cum) {
    int w = threadIdx.x >> 5;
    int l = threadIdx.x & 31;
    const int* src = target + w * TT;
    int* dst = cum + w * TT;
    int v[16];
    int s = 0;
#pragma unroll
    for (int i = 0; i < 16; ++i) { v[i] = src[l * 16 + i]; s += v[i]; }
    int p = s;
#pragma unroll
    for (int off = 1; off < 32; off <<= 1) {
        int u = __shfl_up_sync(0xffffffffu, p, off);
        if (l >= off) p += u;
    }
    int run = p - s;
#pragma unroll
    for (int i = 0; i < 16; ++i) { run += v[i]; dst[l * 16 + i] = run; }
}

// ---------------- length-regulator gather: 64 rows/block ---------------------
__global__ void __launch_bounds__(512, 2)
gather_kernel(const float* __restrict__ x, const int* __restrict__ cum,
              float* __restrict__ out) {
    __shared__ int sc[TT];
    int b = blockIdx.y;
    sc[threadIdx.x] = cum[b * TT + threadIdx.x];
    __syncthreads();
    int total = sc[TT - 1];
    int t_out = blockIdx.x * 64 + (threadIdx.x >> 3);   // 64 rows, 8 threads/row
    int sub   = threadIdx.x & 7;
    int lo = 0, hi = TT;
    while (lo < hi) {
        int mid = (lo + hi) >> 1;
        if (sc[mid] <= t_out) lo = mid + 1; else hi = mid;
    }
    int idx = min(lo, TT - 1);
    bool valid = t_out < total;
    const float4* src = (const float4*)(x + ((size_t)(b * TT + idx)) * DD);
    float4* dst = (float4*)(out + ((size_t)(b * MEL + t_out)) * DD);
    float4 z = make_float4(0.f, 0.f, 0.f, 0.f);
#pragma unroll
    for (int i = 0; i < 8; ++i)
        dst[sub + i * 8] = valid ? src[sub + i * 8] : z;
}

// ---------------- launch ----------------------------------------------------
extern "C" void kernel_launch(void* const* d_in, const int* in_sizes, int n_in,
                              void* d_out, int out_size) {
    const float* x       = (const float*)d_in[0];
    const int*   target  = (const int*)d_in[1];
    const float* conv1_w = (const float*)d_in[3];
    const float* conv1_b = (const float*)d_in[4];
    const float* ln1_g   = (const float*)d_in[5];
    const float* ln1_b   = (const float*)d_in[6];
    const float* conv2_w = (const float*)d_in[7];
    const float* conv2_b = (const float*)d_in[8];
    const float* ln2_g   = (const float*)d_in[9];
    const float* ln2_b   = (const float*)d_in[10];
    const float* lin_w   = (const float*)d_in[11];
    const float* lin_b   = (const float*)d_in[12];

    float* out_gather = (float*)d_out;
    float* out_dur    = (float*)d_out + OUT_GATHER_ELEMS;

    __nv_bfloat16 *w1p, *w2p, *xh, *xl, *h1h, *h1l;
    int* cum;
    cudaGetSymbolAddress((void**)&w1p, g_w1p);
    cudaGetSymbolAddress((void**)&w2p, g_w2p);
    cudaGetSymbolAddress((void**)&xh,  g_xh);
    cudaGetSymbolAddress((void**)&xl,  g_xl);
    cudaGetSymbolAddress((void**)&h1h, g_h1h);
    cudaGetSymbolAddress((void**)&h1l, g_h1l);
    cudaGetSymbolAddress((void**)&cum, g_cum);

    cudaFuncSetAttribute(conv_pipe_kernel<true>,
                         cudaFuncAttributeMaxDynamicSharedMemorySize, CONV_SMEM);
    cudaFuncSetAttribute(conv_pipe_kernel<false>,
                         cudaFuncAttributeMaxDynamicSharedMemorySize, CONV_SMEM);

    pack_all_kernel<<<2 * KTOT + MM * DD / 1024, 256>>>(
        conv1_w, conv2_w, x, w1p, w2p, xh, xl);
    cumsum_kernel<<<1, 1024>>>(target, cum);

    conv_pipe_kernel<true><<<MM / 128, 512, CONV_SMEM>>>(
        xh, xl, w1p,
        conv1_b, ln1_g, ln1_b, lin_w, lin_b, h1h, h1l, nullptr);

    conv_pipe_kernel<false><<<MM / 128, 512, CONV_SMEM>>>(
        h1h, h1l, w2p,
        conv2_b, ln2_g, ln2_b, lin_w, lin_b, nullptr, nullptr, out_dur);

    gather_kernel<<<dim3(MEL / 64, BB), 512>>>(x, cum, out_gather);
}